// round 6
// baseline (speedup 1.0000x reference)
#include <cuda_runtime.h>
#include <math.h>

#define B   16
#define N   1024
#define MP  1024
#define EPS_F     0.1f
#define INV_EPS   10.0f
#define MAX_ITER  100
#define THRESH    0.1f
#define NCHUNK    8          // i-chunks for column LSE (128 rows each)

// ---------------- device scratch (static: no allocations allowed) ----------
__device__ float g_u[B * N];
__device__ float g_v[B * MP];
__device__ float g_absdu[B * N];
__device__ float g_pm[NCHUNK * B * MP];
__device__ float g_ps[NCHUNK * B * MP];
__device__ float g_cost[B];
__device__ int   g_done[2];

// ---------------- init: reset all state every launch (graph replay!) -------
__global__ void k_init() {
    int idx = blockIdx.x * 256 + threadIdx.x;
    if (idx < B * N) { g_u[idx] = 0.f; g_v[idx] = 0.f; }
    if (idx < B)      g_cost[idx] = 0.f;
    if (idx < 2)      g_done[idx] = 0;
}

// ---------------- row update: u_new_i = eps*log_mu - eps*LSE_j((v_j-C_ij)/eps)
// grid 2048 blocks x 256 threads; one warp per row (8 rows / block).
__global__ void k_row(const float* __restrict__ C, int t) {
    if (g_done[t & 1]) return;
    __shared__ float vs[MP];
    int rowBase = blockIdx.x << 3;        // 8 rows per block, batch-aligned
    int b = rowBase >> 10;
    const float* vrow = g_v + (b << 10);
    #pragma unroll
    for (int k = 0; k < 4; k++)
        vs[threadIdx.x + (k << 8)] = vrow[threadIdx.x + (k << 8)];
    __syncthreads();

    int w = threadIdx.x >> 5, lane = threadIdx.x & 31;
    int row = rowBase + w;
    const float4* C4 = (const float4*)(C + ((size_t)row << 10));
    const float4* v4 = (const float4*)vs;

    float a[32];
    #pragma unroll
    for (int k = 0; k < 8; k++) {
        int j = lane + (k << 5);
        float4 c = C4[j];
        float4 vv = v4[j];
        a[4*k+0] = (vv.x - c.x) * INV_EPS;
        a[4*k+1] = (vv.y - c.y) * INV_EPS;
        a[4*k+2] = (vv.z - c.z) * INV_EPS;
        a[4*k+3] = (vv.w - c.w) * INV_EPS;
    }
    float m = a[0];
    #pragma unroll
    for (int k = 1; k < 32; k++) m = fmaxf(m, a[k]);
    #pragma unroll
    for (int off = 16; off; off >>= 1)
        m = fmaxf(m, __shfl_xor_sync(0xffffffffu, m, off));
    float s = 0.f;
    #pragma unroll
    for (int k = 0; k < 32; k++) s += __expf(a[k] - m);
    #pragma unroll
    for (int off = 16; off; off >>= 1)
        s += __shfl_xor_sync(0xffffffffu, s, off);

    if (lane == 0) {
        const float LOG_MARG = logf(1.0f / 1024.0f + 1e-8f);
        float lse   = m + logf(s);
        float u_new = EPS_F * LOG_MARG - EPS_F * lse;
        float u_old = g_u[row];
        g_absdu[row] = fabsf(u_new - u_old);
        g_u[row]     = u_new;
    }
}

// ---------------- column LSE partials + err/done update --------------------
// blocks 0..511: (b, jblk of 256 cols, ichunk of 128 rows) streaming online LSE
// block 512: deterministic err reduction, writes g_done[(t+1)&1]
__global__ void k_colpart(const float* __restrict__ C, int t) {
    int done = g_done[t & 1];
    if (blockIdx.x == 512) {
        __shared__ float sred[256];
        float acc = 0.f;
        if (!done)
            for (int k = threadIdx.x; k < B * N; k += 256) acc += g_absdu[k];
        sred[threadIdx.x] = acc;
        __syncthreads();
        for (int o = 128; o; o >>= 1) {
            if (threadIdx.x < o) sred[threadIdx.x] += sred[threadIdx.x + o];
            __syncthreads();
        }
        if (threadIdx.x == 0) {
            int dn = done;
            if (!dn && (sred[0] * (1.0f / B)) < THRESH) dn = 1;
            g_done[(t + 1) & 1] = dn;
        }
        return;
    }
    if (done) return;

    int blk = blockIdx.x;
    int b      = blk >> 5;
    int rem    = blk & 31;
    int jblk   = rem & 3;
    int ichunk = rem >> 2;
    int j  = (jblk << 8) + threadIdx.x;
    int i0 = ichunk << 7;                 // 128 rows per chunk

    __shared__ float us[128];
    if (threadIdx.x < 128) us[threadIdx.x] = g_u[b * N + i0 + threadIdx.x];
    __syncthreads();

    const float* Cb = C + ((size_t)b * N + i0) * MP + j;
    float m = (us[0] - Cb[0]) * INV_EPS;
    float s = 1.f;
    for (int ii = 1; ii < 128; ii++) {
        float a = (us[ii] - Cb[(size_t)ii * MP]) * INV_EPS;
        if (a > m) { s = s * __expf(m - a) + 1.f; m = a; }
        else       { s += __expf(a - m); }
    }
    int idx = b * MP + j;
    g_pm[ichunk * (B * MP) + idx] = m;
    g_ps[ichunk * (B * MP) + idx] = s;
}

// ---------------- combine column partials -> v_new -------------------------
__global__ void k_colcomb(int t) {
    if (g_done[t & 1]) return;
    int idx = blockIdx.x * 256 + threadIdx.x;   // b*MP + j
    float m = g_pm[idx], s = g_ps[idx];
    #pragma unroll
    for (int k = 1; k < NCHUNK; k++) {
        float m2 = g_pm[k * (B * MP) + idx];
        float s2 = g_ps[k * (B * MP) + idx];
        float nm = fmaxf(m, m2);
        s = s * __expf(m - nm) + s2 * __expf(m2 - nm);
        m = nm;
    }
    const float LOG_MARG = logf(1.0f / 1024.0f + 1e-8f);
    float lse = m + logf(s);
    g_v[idx] = EPS_F * LOG_MARG - EPS_F * lse;
}

// ---------------- epilogue: pi = exp(M), cost = sum(pi*C) per batch --------
__global__ void k_pi(const float* __restrict__ C, float* __restrict__ out_pi) {
    int row = blockIdx.x;
    int b = row >> 10;
    float ue = g_u[row] * INV_EPS;
    const float4* C4 = (const float4*)(C + ((size_t)row << 10));
    const float4* v4 = (const float4*)(g_v + (b << 10));
    float4*       P4 = (float4*)(out_pi + ((size_t)row << 10));
    int j = threadIdx.x;                   // 256 float4 = 1024 floats
    float4 c = C4[j];
    float4 v = v4[j];
    float4 p;
    p.x = __expf((v.x - c.x) * INV_EPS + ue);
    p.y = __expf((v.y - c.y) * INV_EPS + ue);
    p.z = __expf((v.z - c.z) * INV_EPS + ue);
    p.w = __expf((v.w - c.w) * INV_EPS + ue);
    P4[j] = p;
    float acc = p.x * c.x + p.y * c.y + p.z * c.z + p.w * c.w;

    __shared__ float sred[256];
    sred[threadIdx.x] = acc;
    __syncthreads();
    for (int o = 128; o; o >>= 1) {
        if (threadIdx.x < o) sred[threadIdx.x] += sred[threadIdx.x + o];
        __syncthreads();
    }
    if (threadIdx.x == 0) atomicAdd(&g_cost[b], sred[0]);
}

__global__ void k_cost(float* __restrict__ out) {
    if (threadIdx.x < B) out[threadIdx.x] = g_cost[threadIdx.x];
}

// ---------------- launch ----------------------------------------------------
extern "C" void kernel_launch(void* const* d_in, const int* in_sizes, int n_in,
                              void* d_out, int out_size) {
    // inputs: x [16,1024,2], y [16,1024,2], C [16,1024,1024] — pick C by size
    const float* C = nullptr;
    for (int i = 0; i < n_in; i++)
        if (in_sizes[i] == B * N * MP) C = (const float*)d_in[i];
    float* out = (float*)d_out;

    k_init<<<64, 256>>>();
    for (int t = 0; t < MAX_ITER; t++) {
        k_row<<<2048, 256>>>(C, t);
        k_colpart<<<513, 256>>>(C, t);
        k_colcomb<<<64, 256>>>(t);
    }
    k_pi<<<B * N, 256>>>(C, out + B);              // pi at out[16 ..]
    k_cost<<<1, 32>>>(out);                        // cost at out[0..15]
    cudaMemcpyAsync(out + B + (size_t)B * N * MP,  // C passthrough
                    C, (size_t)B * N * MP * sizeof(float),
                    cudaMemcpyDeviceToDevice);
    (void)out_size;
}

// round 7
// speedup vs baseline: 4.1114x; 4.1114x over previous
#include <cuda_runtime.h>
#include <math.h>

#define B   16
#define N   1024
#define MP  1024
#define EPS_F    0.1f
#define INV_EPS  10.0f
#define MAX_ITER 100
#define GRID 256
#define TPB  256

// ---------------- static device scratch (no allocations allowed) ------------
__device__ float g_K[(size_t)B * N * MP];       // 64 MB: exp(-C/eps)
__device__ float g_u[B * N];
__device__ float g_a[B * N];
__device__ float g_b[B * MP];
__device__ float g_part[2][B][16][MP];          // double-buffered column partials
__device__ float g_errpart[2][GRID];
__device__ float g_costpart[GRID];
__device__ int           g_cnt;
__device__ volatile int  g_gen;

// -------- software grid barrier (all GRID blocks guaranteed co-resident) ----
__device__ __forceinline__ void gridbar() {
    __syncthreads();
    if (threadIdx.x == 0) {
        __threadfence();
        int g = g_gen;
        if (atomicAdd(&g_cnt, 1) == GRID - 1) {
            g_cnt = 0;
            __threadfence();
            g_gen = g + 1;
        } else {
            while (g_gen == g) __nanosleep(64);
        }
        __threadfence();
    }
    __syncthreads();
}

__global__ void __launch_bounds__(TPB, 2)
k_sinkhorn(const float* __restrict__ C, float* __restrict__ out)
{
    const int bid = blockIdx.x;
    const int b   = bid >> 4;          // batch 0..15
    const int ib  = bid & 15;          // block-in-batch 0..15
    const int tid = threadIdx.x;
    const int w   = tid >> 5;          // warp 0..7
    const int l   = tid & 31;
    const int rowBase = (b << 10) + (ib << 6);   // 64 rows per block

    __shared__ float sb[MP];           // current b for this batch
    __shared__ float sT[8][MP];        // per-warp column partials
    __shared__ float sred[TPB];

    const float MU   = 1.0f / 1024.0f + 1e-8f;   // mu + 1e-8 (== nu)
    const float LOGM = logf(MU);

    // ---- per-replay init (deterministic reset) ----
    if (tid < 64) g_u[rowBase + tid] = 0.f;
    ((float4*)sb)[tid] = make_float4(1.f, 1.f, 1.f, 1.f);   // b = exp(v0/eps) = 1
    __syncthreads();

    float4*       K4 = (float4*)g_K;
    const float4* C4 = (const float4*)C;

    int par = 0;
    for (int t = 0; t < MAX_ITER; t++) {
        // ================= Phase A: rows (u update) + column partials =======
        float4 Tacc[8];
        #pragma unroll
        for (int k = 0; k < 8; k++) Tacc[k] = make_float4(0.f, 0.f, 0.f, 0.f);
        float du = 0.f;
        const float4* sb4 = (const float4*)sb;

        for (int r = 0; r < 8; r++) {
            int row = rowBase + (w << 3) + r;
            size_t rq = (size_t)row << 8;         // row * 256 quads
            float4 kq[8];
            if (t == 0) {
                #pragma unroll
                for (int k = 0; k < 8; k++) {     // first pass: build K from C
                    float4 c = C4[rq + (k << 5) + l];
                    float4 e;
                    e.x = __expf(-c.x * INV_EPS);
                    e.y = __expf(-c.y * INV_EPS);
                    e.z = __expf(-c.z * INV_EPS);
                    e.w = __expf(-c.w * INV_EPS);
                    kq[k] = e;
                    K4[rq + (k << 5) + l] = e;
                }
            } else {
                #pragma unroll
                for (int k = 0; k < 8; k++) kq[k] = K4[rq + (k << 5) + l];
            }
            // S_i = sum_j K_ij * b_j
            float s = 0.f;
            #pragma unroll
            for (int k = 0; k < 8; k++) {
                float4 bb = sb4[(k << 5) + l];
                s += kq[k].x * bb.x + kq[k].y * bb.y
                   + kq[k].z * bb.z + kq[k].w * bb.w;
            }
            #pragma unroll
            for (int o = 16; o; o >>= 1) s += __shfl_xor_sync(~0u, s, o);

            float a = MU / s;                     // a_i = exp(u_new/eps)
            if (l == 0) {
                float unew = EPS_F * (LOGM - logf(s));
                du += fabsf(unew - g_u[row]);
                g_u[row] = unew;
                g_a[row] = a;
            }
            #pragma unroll
            for (int k = 0; k < 8; k++) {         // T_j += a_i * K_ij
                Tacc[k].x = fmaf(a, kq[k].x, Tacc[k].x);
                Tacc[k].y = fmaf(a, kq[k].y, Tacc[k].y);
                Tacc[k].z = fmaf(a, kq[k].z, Tacc[k].z);
                Tacc[k].w = fmaf(a, kq[k].w, Tacc[k].w);
            }
        }
        // deterministic block-combine of the 8 warps' column partials
        {
            float4* me = (float4*)sT[w];
            #pragma unroll
            for (int k = 0; k < 8; k++) me[(k << 5) + l] = Tacc[k];
            if (l == 0) sred[w] = du;
        }
        __syncthreads();
        {
            float4 Tj = ((float4*)sT[0])[tid];
            #pragma unroll
            for (int ww = 1; ww < 8; ww++) {
                float4 x = ((float4*)sT[ww])[tid];
                Tj.x += x.x; Tj.y += x.y; Tj.z += x.z; Tj.w += x.w;
            }
            ((float4*)g_part[par][b][ib])[tid] = Tj;
        }
        if (tid == 0) {
            float e = 0.f;
            #pragma unroll
            for (int ww = 0; ww < 8; ww++) e += sred[ww];
            g_errpart[par][bid] = e;
        }

        gridbar();

        // ================= Combine: v update (redundant per block) ==========
        float4 T = make_float4(0.f, 0.f, 0.f, 0.f);
        #pragma unroll
        for (int kk = 0; kk < 16; kk++) {
            float4 x = __ldcg(((const float4*)g_part[par][b][kk]) + tid);
            T.x += x.x; T.y += x.y; T.z += x.z; T.w += x.w;
        }
        float4 bb;
        bb.x = MU / T.x; bb.y = MU / T.y; bb.z = MU / T.z; bb.w = MU / T.w;

        // deterministic err reduction (fixed-order tree over 256 partials)
        sred[tid] = __ldcg(&g_errpart[par][tid]);
        __syncthreads();
        for (int o = 128; o; o >>= 1) {
            if (tid < o) sred[tid] += sred[tid + o];
            __syncthreads();
        }
        float err = sred[0];

        ((float4*)sb)[tid] = bb;
        if (ib == 0) ((float4*)g_b)[(b << 8) + tid] = bb;
        __syncthreads();

        if (err < 0.1f * (float)B) break;   // err/B < THRESH  -> freeze & exit
        par ^= 1;
    }

    gridbar();   // g_b / g_a final everywhere

    // ================= Epilogue: pi, cost, C passthrough =====================
    ((float4*)sb)[tid] = __ldcg(((const float4*)g_b) + (b << 8) + tid);
    __syncthreads();

    float*  outCost = out;
    float4* outPi   = (float4*)(out + B);
    float4* outC    = (float4*)(out + B + (size_t)B * N * MP);
    const float4* sb4 = (const float4*)sb;

    float cost = 0.f;
    for (int r = 0; r < 8; r++) {
        int row = rowBase + (w << 3) + r;
        size_t rq = (size_t)row << 8;
        float a = g_a[row];
        #pragma unroll
        for (int k = 0; k < 8; k++) {
            float4 kq = K4[rq + (k << 5) + l];
            float4 c  = C4[rq + (k << 5) + l];
            float4 bb = sb4[(k << 5) + l];
            float4 p;
            p.x = a * kq.x * bb.x;
            p.y = a * kq.y * bb.y;
            p.z = a * kq.z * bb.z;
            p.w = a * kq.w * bb.w;
            outPi[rq + (k << 5) + l] = p;
            outC [rq + (k << 5) + l] = c;
            cost += p.x * c.x + p.y * c.y + p.z * c.z + p.w * c.w;
        }
    }
    sred[tid] = cost;
    __syncthreads();
    for (int o = 128; o; o >>= 1) {
        if (tid < o) sred[tid] += sred[tid + o];
        __syncthreads();
    }
    if (tid == 0) g_costpart[bid] = sred[0];

    gridbar();

    if (bid == 0 && tid < B) {        // deterministic final cost sum
        float cs = 0.f;
        #pragma unroll
        for (int kk = 0; kk < 16; kk++)
            cs += __ldcg(&g_costpart[(tid << 4) + kk]);
        outCost[tid] = cs;
    }
}

// ---------------- launch -----------------------------------------------------
extern "C" void kernel_launch(void* const* d_in, const int* in_sizes, int n_in,
                              void* d_out, int out_size) {
    const float* C = nullptr;
    for (int i = 0; i < n_in; i++)
        if (in_sizes[i] == B * N * MP) C = (const float*)d_in[i];
    k_sinkhorn<<<GRID, TPB>>>(C, (float*)d_out);
    (void)out_size;
}

// round 8
// speedup vs baseline: 8.1497x; 1.9822x over previous
#include <cuda_runtime.h>
#include <cuda_fp16.h>
#include <math.h>

#define B   16
#define N   1024
#define MP  1024
#define EPS_F    0.1f
#define INV_EPS  10.0f
#define MAX_ITER 100
#define GRID 128            // 16 batches x 8 blocks; 1 CTA/SM -> all co-resident
#define TPB  256
#define RPB  128            // rows per block
#define RPW  16             // rows per warp
#define PB   8              // blocks per batch

// ---------------- static device scratch (no allocations allowed) ------------
__device__ __half g_Kh[(size_t)B * N * MP];     // 32 MB: exp(-C/eps) in fp16
__device__ float  g_part[2][B][PB][MP];         // double-buffered column partials
__device__ float  g_errpart[2][GRID];
__device__ float  g_costpart[GRID];
__device__ int          g_cnt;
__device__ volatile int g_gen;

// -------- software grid barrier (128 blocks, 1/SM, guaranteed resident) -----
__device__ __forceinline__ void gridbar() {
    __syncthreads();
    if (threadIdx.x == 0) {
        __threadfence();
        int g = g_gen;
        if (atomicAdd(&g_cnt, 1) == GRID - 1) {
            g_cnt = 0;
            __threadfence();
            g_gen = g + 1;
        } else {
            while (g_gen == g) __nanosleep(64);
        }
        __threadfence();
    }
    __syncthreads();
}

__device__ __forceinline__ void h8_to_f8(const uint4 v, float* f) {
    float2 a = __half22float2(*(const __half2*)&v.x);
    float2 b = __half22float2(*(const __half2*)&v.y);
    float2 c = __half22float2(*(const __half2*)&v.z);
    float2 d = __half22float2(*(const __half2*)&v.w);
    f[0]=a.x; f[1]=a.y; f[2]=b.x; f[3]=b.y; f[4]=c.x; f[5]=c.y; f[6]=d.x; f[7]=d.y;
}

__global__ void __launch_bounds__(TPB, 1)
k_sinkhorn(const float* __restrict__ C, float* __restrict__ out)
{
    const int bid = blockIdx.x;
    const int b   = bid >> 3;            // batch 0..15
    const int ib  = bid & 7;             // block-in-batch 0..7
    const int tid = threadIdx.x;
    const int w   = tid >> 5;            // warp 0..7
    const int l   = tid & 31;
    const int rowBase = (b << 10) + (ib << 7);   // 128 rows per block
    const int wrow    = rowBase + w * RPW;       // this warp's 16 rows

    __shared__ float sb[MP];             // current b (exp(v/eps)) for this batch
    __shared__ float sT[8][MP];          // per-warp column partials
    __shared__ float sU[RPB];            // u values for this block's rows
    __shared__ float sA[RPB];            // a = exp(u/eps) for this block's rows
    __shared__ float sred[TPB];

    const float MU   = 1.0f / 1024.0f + 1e-8f;
    const float LOGM = logf(MU);

    // ---- per-replay init ----
    if (tid < RPB) { sU[tid] = 0.f; sA[tid] = 0.f; }
    ((float4*)sb)[tid] = make_float4(1.f, 1.f, 1.f, 1.f);   // b0 = 1
    __syncthreads();

    uint4*        K4 = (uint4*)g_Kh;     // 8 halfs/uint4, 128 uint4 per row
    const float4* C4 = (const float4*)C; // 256 float4 per row

    int par = 0;
    for (int t = 0; t < MAX_ITER; t++) {
        // -------- cache b in registers: lane covers cols (k*32+l)*8 + e -----
        float bb[4][8];
        #pragma unroll
        for (int k = 0; k < 4; k++) {
            float4 p0 = ((const float4*)sb)[(((k << 5) + l) << 1)];
            float4 p1 = ((const float4*)sb)[(((k << 5) + l) << 1) + 1];
            bb[k][0]=p0.x; bb[k][1]=p0.y; bb[k][2]=p0.z; bb[k][3]=p0.w;
            bb[k][4]=p1.x; bb[k][5]=p1.y; bb[k][6]=p1.z; bb[k][7]=p1.w;
        }
        float Tacc[4][8];
        #pragma unroll
        for (int k = 0; k < 4; k++)
            #pragma unroll
            for (int e = 0; e < 8; e++) Tacc[k][e] = 0.f;
        float du = 0.f;

        if (t == 0) {
            // ---- first pass: build fp16 K from C while iterating ----
            for (int r = 0; r < RPW; r++) {
                size_t qb = (size_t)(wrow + r) << 7;
                float kf[4][8];
                #pragma unroll
                for (int k = 0; k < 4; k++) {
                    size_t q = qb + (k << 5) + l;
                    float4 c0 = C4[q << 1];
                    float4 c1 = C4[(q << 1) + 1];
                    kf[k][0]=__expf(-c0.x*INV_EPS); kf[k][1]=__expf(-c0.y*INV_EPS);
                    kf[k][2]=__expf(-c0.z*INV_EPS); kf[k][3]=__expf(-c0.w*INV_EPS);
                    kf[k][4]=__expf(-c1.x*INV_EPS); kf[k][5]=__expf(-c1.y*INV_EPS);
                    kf[k][6]=__expf(-c1.z*INV_EPS); kf[k][7]=__expf(-c1.w*INV_EPS);
                    uint4 kv;
                    __half2 h;
                    h=__floats2half2_rn(kf[k][0],kf[k][1]); kv.x=*(unsigned*)&h;
                    h=__floats2half2_rn(kf[k][2],kf[k][3]); kv.y=*(unsigned*)&h;
                    h=__floats2half2_rn(kf[k][4],kf[k][5]); kv.z=*(unsigned*)&h;
                    h=__floats2half2_rn(kf[k][6],kf[k][7]); kv.w=*(unsigned*)&h;
                    K4[q] = kv;
                    // use the fp16-rounded values so iterations are consistent
                    h8_to_f8(kv, kf[k]);
                }
                float s = 0.f;
                #pragma unroll
                for (int k = 0; k < 4; k++)
                    #pragma unroll
                    for (int e = 0; e < 8; e++) s = fmaf(kf[k][e], bb[k][e], s);
                #pragma unroll
                for (int o = 16; o; o >>= 1) s += __shfl_xor_sync(~0u, s, o);
                float a = MU / s;
                if (l == 0) {
                    float unew = EPS_F * (LOGM - logf(s));
                    int ri = w * RPW + r;
                    du += fabsf(unew - sU[ri]);
                    sU[ri] = unew; sA[ri] = a;
                }
                #pragma unroll
                for (int k = 0; k < 4; k++)
                    #pragma unroll
                    for (int e = 0; e < 8; e++)
                        Tacc[k][e] = fmaf(a, kf[k][e], Tacc[k][e]);
            }
        } else {
            // ---- steady state: fp16 K, double-buffered loads ----
            uint4 kq[4];
            {
                size_t qb = (size_t)wrow << 7;
                #pragma unroll
                for (int k = 0; k < 4; k++) kq[k] = K4[qb + (k << 5) + l];
            }
            for (int r = 0; r < RPW; r++) {
                uint4 kn[4];
                if (r + 1 < RPW) {
                    size_t qn = (size_t)(wrow + r + 1) << 7;
                    #pragma unroll
                    for (int k = 0; k < 4; k++) kn[k] = K4[qn + (k << 5) + l];
                }
                float kf[4][8];
                #pragma unroll
                for (int k = 0; k < 4; k++) h8_to_f8(kq[k], kf[k]);
                float s = 0.f;
                #pragma unroll
                for (int k = 0; k < 4; k++)
                    #pragma unroll
                    for (int e = 0; e < 8; e++) s = fmaf(kf[k][e], bb[k][e], s);
                #pragma unroll
                for (int o = 16; o; o >>= 1) s += __shfl_xor_sync(~0u, s, o);
                float a = MU / s;
                if (l == 0) {
                    float unew = EPS_F * (LOGM - logf(s));
                    int ri = w * RPW + r;
                    du += fabsf(unew - sU[ri]);
                    sU[ri] = unew; sA[ri] = a;
                }
                #pragma unroll
                for (int k = 0; k < 4; k++)
                    #pragma unroll
                    for (int e = 0; e < 8; e++)
                        Tacc[k][e] = fmaf(a, kf[k][e], Tacc[k][e]);
                if (r + 1 < RPW) {
                    #pragma unroll
                    for (int k = 0; k < 4; k++) kq[k] = kn[k];
                }
            }
        }

        // -------- block-combine 8 warps' column partials (deterministic) ----
        {
            float4* me = (float4*)sT[w];
            #pragma unroll
            for (int k = 0; k < 4; k++) {
                me[(((k << 5) + l) << 1)]     = make_float4(Tacc[k][0], Tacc[k][1], Tacc[k][2], Tacc[k][3]);
                me[(((k << 5) + l) << 1) + 1] = make_float4(Tacc[k][4], Tacc[k][5], Tacc[k][6], Tacc[k][7]);
            }
            if (l == 0) sred[w] = du;
        }
        __syncthreads();
        {
            float4 Tj = ((const float4*)sT[0])[tid];
            #pragma unroll
            for (int ww = 1; ww < 8; ww++) {
                float4 x = ((const float4*)sT[ww])[tid];
                Tj.x += x.x; Tj.y += x.y; Tj.z += x.z; Tj.w += x.w;
            }
            ((float4*)g_part[par][b][ib])[tid] = Tj;
        }
        if (tid == 0) {
            float e = 0.f;
            #pragma unroll
            for (int ww = 0; ww < 8; ww++) e += sred[ww];
            g_errpart[par][bid] = e;
        }

        gridbar();

        // -------- v update: combine 8 block-partials (redundant per block) --
        float4 T = make_float4(0.f, 0.f, 0.f, 0.f);
        #pragma unroll
        for (int kk = 0; kk < PB; kk++) {
            float4 x = __ldcg(((const float4*)g_part[par][b][kk]) + tid);
            T.x += x.x; T.y += x.y; T.z += x.z; T.w += x.w;
        }
        float4 bbn;
        bbn.x = MU / T.x; bbn.y = MU / T.y; bbn.z = MU / T.z; bbn.w = MU / T.w;

        // deterministic err reduction
        sred[tid] = (tid < GRID) ? __ldcg(&g_errpart[par][tid]) : 0.f;
        __syncthreads();
        for (int o = 128; o; o >>= 1) {
            if (tid < o) sred[tid] += sred[tid + o];
            __syncthreads();
        }
        float err = sred[0];

        ((float4*)sb)[tid] = bbn;
        __syncthreads();

        if (err < 0.1f * (float)B) break;    // err/B < THRESH
        par ^= 1;
    }

    // ============= Epilogue: pi = a*b*exp(-C/eps), cost, C copy =============
    float*  outCost = out;
    float4* outPi   = (float4*)(out + B);
    float4* outC    = (float4*)(out + B + (size_t)B * N * MP);
    const float4* sb4 = (const float4*)sb;

    float cost = 0.f;
    for (int r = 0; r < RPW; r++) {
        int row = wrow + r;
        size_t f4 = (size_t)row << 8;
        float a = sA[w * RPW + r];
        #pragma unroll
        for (int k = 0; k < 8; k++) {
            int q = (k << 5) + l;
            float4 c  = C4[f4 + q];
            float4 bv = sb4[q];
            float4 p;
            p.x = a * bv.x * __expf(-c.x * INV_EPS);
            p.y = a * bv.y * __expf(-c.y * INV_EPS);
            p.z = a * bv.z * __expf(-c.z * INV_EPS);
            p.w = a * bv.w * __expf(-c.w * INV_EPS);
            outPi[f4 + q] = p;
            outC [f4 + q] = c;
            cost += p.x * c.x + p.y * c.y + p.z * c.z + p.w * c.w;
        }
    }
    sred[tid] = cost;
    __syncthreads();
    for (int o = 128; o; o >>= 1) {
        if (tid < o) sred[tid] += sred[tid + o];
        __syncthreads();
    }
    if (tid == 0) g_costpart[bid] = sred[0];

    gridbar();

    if (bid == 0 && tid < B) {               // deterministic final cost sum
        float cs = 0.f;
        #pragma unroll
        for (int kk = 0; kk < PB; kk++)
            cs += __ldcg(&g_costpart[(tid << 3) + kk]);
        outCost[tid] = cs;
    }
}

// ---------------- launch -----------------------------------------------------
extern "C" void kernel_launch(void* const* d_in, const int* in_sizes, int n_in,
                              void* d_out, int out_size) {
    const float* C = nullptr;
    for (int i = 0; i < n_in; i++)
        if (in_sizes[i] == B * N * MP) C = (const float*)d_in[i];
    k_sinkhorn<<<GRID, TPB>>>(C, (float*)d_out);
    (void)out_size;
}